// round 1
// baseline (speedup 1.0000x reference)
#include <cuda_runtime.h>
#include <cuda_bf16.h>

#ifndef LR
#define LR 0.01f
#endif

// Fast path: C == 4, one thread per batch row, float4 vector loads.
// u <- a*u + c applied 100 times, composed into 25 applications of the
// exact 4-step affine map (a4, c4).
__global__ void diffmpc2_c4_kernel(const float* __restrict__ Q,
                                   const float* __restrict__ P,
                                   const float4* __restrict__ U0,
                                   float4* __restrict__ OUT,
                                   int B, int row_len) {
    int b = blockIdx.x * blockDim.x + threadIdx.x;
    if (b >= B) return;

    size_t off = (size_t)b * (size_t)row_len + (size_t)(row_len - 4);
    const float4 q = *reinterpret_cast<const float4*>(Q + off);
    const float4 p = *reinterpret_cast<const float4*>(P + off);
    float4 u = U0[b];

    // a = 1 - 2*LR*q ; c = -LR*p
    float4 a, c;
    a.x = fmaf(-2.0f * LR, q.x, 1.0f);
    a.y = fmaf(-2.0f * LR, q.y, 1.0f);
    a.z = fmaf(-2.0f * LR, q.z, 1.0f);
    a.w = fmaf(-2.0f * LR, q.w, 1.0f);
    c.x = -LR * p.x; c.y = -LR * p.y; c.z = -LR * p.z; c.w = -LR * p.w;

    // Compose 2 steps: (a,c) -> (a^2, a*c + c). Twice -> exact 4-step map.
    float4 a2, c2;
    a2.x = a.x * a.x; c2.x = fmaf(a.x, c.x, c.x);
    a2.y = a.y * a.y; c2.y = fmaf(a.y, c.y, c.y);
    a2.z = a.z * a.z; c2.z = fmaf(a.z, c.z, c.z);
    a2.w = a.w * a.w; c2.w = fmaf(a.w, c.w, c.w);

    float4 a4, c4;
    a4.x = a2.x * a2.x; c4.x = fmaf(a2.x, c2.x, c2.x);
    a4.y = a2.y * a2.y; c4.y = fmaf(a2.y, c2.y, c2.y);
    a4.z = a2.z * a2.z; c4.z = fmaf(a2.z, c2.z, c2.z);
    a4.w = a2.w * a2.w; c4.w = fmaf(a2.w, c2.w, c2.w);

    // 25 x 4-step map = 100 steps. 4 independent FMA chains per thread.
#pragma unroll
    for (int i = 0; i < 25; i++) {
        u.x = fmaf(a4.x, u.x, c4.x);
        u.y = fmaf(a4.y, u.y, c4.y);
        u.z = fmaf(a4.z, u.z, c4.z);
        u.w = fmaf(a4.w, u.w, c4.w);
    }

    OUT[b] = u;
}

// Generic fallback: one thread per (b, j) element, same composed math.
__global__ void diffmpc2_gen_kernel(const float* __restrict__ Q,
                                    const float* __restrict__ P,
                                    const float* __restrict__ U0,
                                    float* __restrict__ OUT,
                                    int B, int S, int C) {
    int e = blockIdx.x * blockDim.x + threadIdx.x;
    if (e >= B * C) return;
    int b = e / C;
    int j = e - b * C;
    size_t off = (size_t)b * (size_t)(S + C) + (size_t)(S + j);

    float q = Q[off];
    float p = P[off];
    float u = U0[e];

    float a = fmaf(-2.0f * LR, q, 1.0f);
    float c = -LR * p;
    float a2 = a * a,   c2 = fmaf(a, c, c);
    float a4 = a2 * a2, c4 = fmaf(a2, c2, c2);
#pragma unroll
    for (int i = 0; i < 25; i++) u = fmaf(a4, u, c4);
    OUT[e] = u;
}

extern "C" void kernel_launch(void* const* d_in, const int* in_sizes, int n_in,
                              void* d_out, int out_size) {
    // inputs: x_init [B,S] (unused), Q [B,S+C], p [B,S+C], u_init [B,C]
    const float* Q  = (const float*)d_in[1];
    const float* P  = (const float*)d_in[2];
    const float* U0 = (const float*)d_in[3];
    float* OUT = (float*)d_out;

    // Derive shapes. out_size = B*C ; in_sizes[0] = B*S ; in_sizes[1] = B*(S+C)
    // Assume C = 4 (reference shapes). Then:
    int C = 4;
    int B = out_size / C;
    int S = in_sizes[0] / B;
    int row_len = S + C;

    // Sanity: if the derived shapes are inconsistent, fall back to generic
    // with C recomputed from consistency (B*C == out_size, B*(S+C) == sizes[1]).
    bool c4_ok = (B * C == out_size) && ((size_t)B * row_len == (size_t)in_sizes[1])
                 && (B * S == in_sizes[0]);

    if (c4_ok) {
        int threads = 256;
        int blocks = (B + threads - 1) / threads;
        diffmpc2_c4_kernel<<<blocks, threads>>>(
            Q, P, (const float4*)U0, (float4*)OUT, B, row_len);
    } else {
        // Generic: solve B,S,C from sizes assuming in_sizes[3] = B*C.
        // gcd-free heuristic: try C from 1..64 such that everything divides.
        int Bc = 0, Sc = 0, Cc = 0;
        for (int c = 1; c <= 64; c++) {
            if (out_size % c) continue;
            int b = out_size / c;
            if (in_sizes[0] % b) continue;
            int s = in_sizes[0] / b;
            if ((size_t)b * (size_t)(s + c) == (size_t)in_sizes[1]) {
                Bc = b; Sc = s; Cc = c; break;
            }
        }
        int total = out_size;
        int threads = 256;
        int blocks = (total + threads - 1) / threads;
        diffmpc2_gen_kernel<<<blocks, threads>>>(Q, P, U0, OUT, Bc, Sc, Cc);
    }
}